// round 11
// baseline (speedup 1.0000x reference)
#include <cuda_runtime.h>
#include <cuda_fp16.h>
#include <cuda_bf16.h>

#define NN 4
#define NQ 256
#define NV 512
#define NE 256

// Scratch (allocation-free requirement)
__device__ float g_expl[NN * NQ * NV];       // exp(logit/t)  (2 MB)
__device__ float g_denp[NN * NQ * 8];        // per-64v denominator partials
__device__ float g_pvp2[2][NN * NQ * NE];    // split-2 partials of exp@memory (2 MB)

// ---------------------------------------------------------------------------
// helpers
// ---------------------------------------------------------------------------
__device__ __forceinline__ uint4 pack8(const float4 a, const float4 b) {
    __half2 h0 = __floats2half2_rn(a.x, a.y);
    __half2 h1 = __floats2half2_rn(a.z, a.w);
    __half2 h2 = __floats2half2_rn(b.x, b.y);
    __half2 h3 = __floats2half2_rn(b.z, b.w);
    uint4 r;
    r.x = *reinterpret_cast<unsigned*>(&h0);
    r.y = *reinterpret_cast<unsigned*>(&h1);
    r.z = *reinterpret_cast<unsigned*>(&h2);
    r.w = *reinterpret_cast<unsigned*>(&h3);
    return r;
}

__device__ __forceinline__ __half2 u2h(unsigned u) {
    return *reinterpret_cast<__half2*>(&u);
}

__device__ __forceinline__ __half2 wtanh(unsigned cv, unsigned qv, unsigned wv) {
    __half2 s = __hadd2(u2h(qv), u2h(cv));
    unsigned su = *reinterpret_cast<unsigned*>(&s);
    unsigned tu;
    asm("tanh.approx.f16x2 %0, %1;" : "=r"(tu) : "r"(su));
    return __hmul2(u2h(tu), u2h(wv));
}

// tf32 helpers
__device__ __forceinline__ unsigned f2tf(float f) {
    unsigned u;
    asm("cvt.rna.tf32.f32 %0, %1;" : "=r"(u) : "f"(f));
    return u;
}
// split f into tf32 hi + tf32 lo (residual)
__device__ __forceinline__ void tfsplit(float f, unsigned& hi, unsigned& lo) {
    hi = f2tf(f);
    float r = f - __uint_as_float(hi);
    lo = f2tf(r);
}
__device__ __forceinline__ void mma_tf32(float* c,
    unsigned a0, unsigned a1, unsigned a2, unsigned a3,
    unsigned b0, unsigned b1) {
    asm("mma.sync.aligned.m16n8k8.row.col.f32.tf32.tf32.f32 "
        "{%0,%1,%2,%3}, {%4,%5,%6,%7}, {%8,%9}, {%0,%1,%2,%3};"
        : "+f"(c[0]), "+f"(c[1]), "+f"(c[2]), "+f"(c[3])
        : "r"(a0), "r"(a1), "r"(a2), "r"(a3), "r"(b0), "r"(b1));
}

// ---------------------------------------------------------------------------
// K1: e[n,q,v] = exp( (sum_e w*tanh(q+c) + b) / t ), plus per-64v denom
// partials. EXACT r7 body (best measured config).
// ---------------------------------------------------------------------------
__global__ void __launch_bounds__(256) k_logits(
    const float* __restrict__ q, const float* __restrict__ c,
    const float* __restrict__ wl, const float* __restrict__ bl_p,
    const float* __restrict__ temp_p)
{
    __shared__ uint4 ct[32][33];
    __shared__ uint4 qs[8][32];
    __shared__ uint4 ws[32];

    const int n = blockIdx.z;
    const int qbase = blockIdx.x * 8;
    const int tid = threadIdx.x;
    const int wq = tid >> 5, lane = tid & 31;

    {
        int r = tid >> 5, g = tid & 31;
        const float4* src =
            (const float4*)&q[((size_t)n * NQ + qbase + r) * NE + g * 8];
        qs[r][g] = pack8(src[0], src[1]);
    }
    if (tid < 32) {
        const float4* src = (const float4*)&wl[tid * 8];
        ws[tid] = pack8(src[0], src[1]);
    }
    const float bl = __ldg(bl_p);
    const float invt = 1.0f / __ldg(temp_p);

    float dsum = 0.f;
    #pragma unroll
    for (int t = 0; t < 2; ++t) {
        __syncthreads();
        const int vbase = blockIdx.y * 64 + t * 32;
        for (int i = tid; i < 1024; i += 256) {
            int v = i >> 5, g = i & 31;
            const float4* src =
                (const float4*)&c[((size_t)n * NV + vbase + v) * NE + g * 8];
            ct[g][v] = pack8(src[0], src[1]);
        }
        __syncthreads();

        float a0 = 0.f, a1 = 0.f;
        #pragma unroll 8
        for (int g = 0; g < 32; ++g) {
            uint4 cb = ct[g][lane];
            uint4 qb = qs[wq][g];
            uint4 wb = ws[g];
            __half2 p0 = wtanh(cb.x, qb.x, wb.x);
            __half2 p1 = wtanh(cb.y, qb.y, wb.y);
            __half2 p2 = wtanh(cb.z, qb.z, wb.z);
            __half2 p3 = wtanh(cb.w, qb.w, wb.w);
            __half2 ps = __hadd2(__hadd2(p0, p1), __hadd2(p2, p3));
            float2 f = __half22float2(ps);
            a0 += f.x;
            a1 += f.y;
        }
        float e = __expf((a0 + a1 + bl) * invt);
        dsum += e;
        g_expl[((size_t)n * NQ + qbase + wq) * NV + vbase + lane] = e;
    }

    #pragma unroll
    for (int o = 16; o; o >>= 1) dsum += __shfl_xor_sync(0xffffffffu, dsum, o);
    if (lane == 0)
        g_denp[((size_t)n * NQ + qbase + wq) * 8 + blockIdx.y] = dsum;
}

// ---------------------------------------------------------------------------
// K2: split-2 of exp @ memory via tf32 mma (3-term residual = ~fp32 exact).
// 64x64 tile, 128 threads (4 warps, 2x2 warp grid, 32x32 warp tiles).
// Register-prefetch double buffering over BK=16 chunks.
// ---------------------------------------------------------------------------
__global__ void __launch_bounds__(128) k_pv(const float* __restrict__ Mm)
{
    const int n = blockIdx.z >> 1, s = blockIdx.z & 1;
    const int m0 = blockIdx.y * 64, n0 = blockIdx.x * 64;
    const float* A = g_expl + (size_t)n * NQ * NV;   // [256][512]
    const float* B = Mm + (size_t)n * NV * NE;       // [512][256]

    __shared__ float As[16][68];   // [k][m]
    __shared__ float Bs[16][68];   // [k][n]

    const int tid = threadIdx.x;
    const int wid = tid >> 5, lane = tid & 31;
    const int wm = wid >> 1, wn = wid & 1;
    const int g = lane >> 2, tig = lane & 3;

    // staging map
    const int ar = tid >> 1, acH = (tid & 1) * 8;    // A: 64 rows x 16 k
    const int bkr = tid >> 3, bnc = (tid & 7) * 8;   // B: 16 k x 64 n

    float acc[2][4][4] = {};

    const int kbase = s * 256;
    float4 pa0, pa1, pb0, pb1;
    {   // prefetch tile 0
        const float* ap = &A[(size_t)(m0 + ar) * NV + kbase + acH];
        pa0 = *(const float4*)ap; pa1 = *(const float4*)(ap + 4);
        const float* bp = &B[(size_t)(kbase + bkr) * NE + n0 + bnc];
        pb0 = *(const float4*)bp; pb1 = *(const float4*)(bp + 4);
    }

    #pragma unroll 1
    for (int it = 0; it < 16; ++it) {
        // store staged regs to smem
        As[acH + 0][ar] = pa0.x; As[acH + 1][ar] = pa0.y;
        As[acH + 2][ar] = pa0.z; As[acH + 3][ar] = pa0.w;
        As[acH + 4][ar] = pa1.x; As[acH + 5][ar] = pa1.y;
        As[acH + 6][ar] = pa1.z; As[acH + 7][ar] = pa1.w;
        *(float4*)&Bs[bkr][bnc] = pb0;
        *(float4*)&Bs[bkr][bnc + 4] = pb1;
        __syncthreads();

        if (it < 15) {  // prefetch next tile (overlaps compute)
            const int k0 = kbase + (it + 1) * 16;
            const float* ap = &A[(size_t)(m0 + ar) * NV + k0 + acH];
            pa0 = *(const float4*)ap; pa1 = *(const float4*)(ap + 4);
            const float* bp = &B[(size_t)(k0 + bkr) * NE + n0 + bnc];
            pb0 = *(const float4*)bp; pb1 = *(const float4*)(bp + 4);
        }

        #pragma unroll
        for (int kc = 0; kc < 2; ++kc) {
            const int kr = kc * 8 + tig;
            // A fragments (2 m16 tiles), hi/lo
            unsigned ah[2][4], al[2][4];
            #pragma unroll
            for (int mt = 0; mt < 2; ++mt) {
                const int cm = wm * 32 + mt * 16 + g;
                tfsplit(As[kr][cm],         ah[mt][0], al[mt][0]);
                tfsplit(As[kr][cm + 8],     ah[mt][1], al[mt][1]);
                tfsplit(As[kr + 4][cm],     ah[mt][2], al[mt][2]);
                tfsplit(As[kr + 4][cm + 8], ah[mt][3], al[mt][3]);
            }
            // B fragments (4 n8 tiles), hi/lo
            unsigned bh[4][2], blo[4][2];
            #pragma unroll
            for (int nt = 0; nt < 4; ++nt) {
                const int cn = wn * 32 + nt * 8 + g;
                tfsplit(Bs[kr][cn],     bh[nt][0], blo[nt][0]);
                tfsplit(Bs[kr + 4][cn], bh[nt][1], blo[nt][1]);
            }
            #pragma unroll
            for (int mt = 0; mt < 2; ++mt)
                #pragma unroll
                for (int nt = 0; nt < 4; ++nt) {
                    float* c = acc[mt][nt];
                    mma_tf32(c, ah[mt][0], ah[mt][1], ah[mt][2], ah[mt][3],
                             bh[nt][0], bh[nt][1]);
                    mma_tf32(c, al[mt][0], al[mt][1], al[mt][2], al[mt][3],
                             bh[nt][0], bh[nt][1]);
                    mma_tf32(c, ah[mt][0], ah[mt][1], ah[mt][2], ah[mt][3],
                             blo[nt][0], blo[nt][1]);
                }
        }
        __syncthreads();
    }

    float* P = g_pvp2[s] + (size_t)n * NQ * NE;
    #pragma unroll
    for (int mt = 0; mt < 2; ++mt) {
        const int r0 = m0 + wm * 32 + mt * 16 + g;
        #pragma unroll
        for (int nt = 0; nt < 4; ++nt) {
            const int cc = n0 + wn * 32 + nt * 8 + 2 * tig;
            float* c = acc[mt][nt];
            *(float2*)&P[(size_t)r0 * NE + cc] = make_float2(c[0], c[1]);
            *(float2*)&P[(size_t)(r0 + 8) * NE + cc] = make_float2(c[2], c[3]);
        }
    }
}

// ---------------------------------------------------------------------------
// K3: out = leaky((pvp0+pvp1)/den) @ Wr^T + bias, tf32 mma, K=256.
// merge (partial sum + normalize + leaky) fused into A-staging;
// bias fused into epilogue. 64 blocks.
// ---------------------------------------------------------------------------
__global__ void __launch_bounds__(128) k_out(
    const float* __restrict__ Wr, const float* __restrict__ br_p,
    float* __restrict__ out)
{
    const int n = blockIdx.z;
    const int m0 = blockIdx.y * 64, n0 = blockIdx.x * 64;
    const size_t abase = (size_t)n * NQ * NE;

    __shared__ float As[16][68];   // [k][m] heads
    __shared__ float Bs[16][68];   // [k][j] Wr^T

    const int tid = threadIdx.x;
    const int wid = tid >> 5, lane = tid & 31;
    const int wm = wid >> 1, wn = wid & 1;
    const int g = lane >> 2, tig = lane & 3;

    const int ar = tid >> 1, acH = (tid & 1) * 8;    // A: 64 rows x 16 k

    // per-thread row denominator (row fixed for all k-iters)
    float dt = 0.f;
    #pragma unroll
    for (int vb = 0; vb < 8; ++vb)
        dt += g_denp[((size_t)n * NQ + m0 + ar) * 8 + vb];
    const float inv = 1.0f / dt;

    float acc[2][4][4] = {};

    float4 ha0, ha1, wb0, wb1;
    {   // prefetch tile 0
        const size_t ai = abase + (size_t)(m0 + ar) * NE + acH;
        float4 p00 = *(const float4*)&g_pvp2[0][ai];
        float4 p01 = *(const float4*)&g_pvp2[0][ai + 4];
        float4 p10 = *(const float4*)&g_pvp2[1][ai];
        float4 p11 = *(const float4*)&g_pvp2[1][ai + 4];
        ha0 = make_float4(p00.x + p10.x, p00.y + p10.y, p00.z + p10.z, p00.w + p10.w);
        ha1 = make_float4(p01.x + p11.x, p01.y + p11.y, p01.z + p11.z, p01.w + p11.w);
        const float* wp = &Wr[(size_t)(n0 + ar) * NE + acH];
        wb0 = *(const float4*)wp; wb1 = *(const float4*)(wp + 4);
    }

    #pragma unroll 1
    for (int it = 0; it < 16; ++it) {
        // A: normalize + leaky during staging store
        float hv[8] = {ha0.x, ha0.y, ha0.z, ha0.w, ha1.x, ha1.y, ha1.z, ha1.w};
        #pragma unroll
        for (int j = 0; j < 8; ++j) {
            float h = hv[j] * inv;
            As[acH + j][ar] = (h > 0.f) ? h : 0.01f * h;
        }
        // B transpose store: Bs[k][j] = Wr[(n0+j)][k]
        float wv[8] = {wb0.x, wb0.y, wb0.z, wb0.w, wb1.x, wb1.y, wb1.z, wb1.w};
        #pragma unroll
        for (int j = 0; j < 8; ++j)
            Bs[acH + j][ar] = wv[j];
        __syncthreads();

        if (it < 15) {
            const int k0 = (it + 1) * 16;
            const size_t ai = abase + (size_t)(m0 + ar) * NE + k0 + acH;
            float4 p00 = *(const float4*)&g_pvp2[0][ai];
            float4 p01 = *(const float4*)&g_pvp2[0][ai + 4];
            float4 p10 = *(const float4*)&g_pvp2[1][ai];
            float4 p11 = *(const float4*)&g_pvp2[1][ai + 4];
            ha0 = make_float4(p00.x + p10.x, p00.y + p10.y, p00.z + p10.z, p00.w + p10.w);
            ha1 = make_float4(p01.x + p11.x, p01.y + p11.y, p01.z + p11.z, p01.w + p11.w);
            const float* wp = &Wr[(size_t)(n0 + ar) * NE + k0 + acH];
            wb0 = *(const float4*)wp; wb1 = *(const float4*)(wp + 4);
        }

        #pragma unroll
        for (int kc = 0; kc < 2; ++kc) {
            const int kr = kc * 8 + tig;
            unsigned ah[2][4], al[2][4];
            #pragma unroll
            for (int mt = 0; mt < 2; ++mt) {
                const int cm = wm * 32 + mt * 16 + g;
                tfsplit(As[kr][cm],         ah[mt][0], al[mt][0]);
                tfsplit(As[kr][cm + 8],     ah[mt][1], al[mt][1]);
                tfsplit(As[kr + 4][cm],     ah[mt][2], al[mt][2]);
                tfsplit(As[kr + 4][cm + 8], ah[mt][3], al[mt][3]);
            }
            unsigned bh[4][2], blo[4][2];
            #pragma unroll
            for (int nt = 0; nt < 4; ++nt) {
                const int cn = wn * 32 + nt * 8 + g;
                tfsplit(Bs[kr][cn],     bh[nt][0], blo[nt][0]);
                tfsplit(Bs[kr + 4][cn], bh[nt][1], blo[nt][1]);
            }
            #pragma unroll
            for (int mt = 0; mt < 2; ++mt)
                #pragma unroll
                for (int nt = 0; nt < 4; ++nt) {
                    float* c = acc[mt][nt];
                    mma_tf32(c, ah[mt][0], ah[mt][1], ah[mt][2], ah[mt][3],
                             bh[nt][0], bh[nt][1]);
                    mma_tf32(c, al[mt][0], al[mt][1], al[mt][2], al[mt][3],
                             bh[nt][0], bh[nt][1]);
                    mma_tf32(c, ah[mt][0], ah[mt][1], ah[mt][2], ah[mt][3],
                             blo[nt][0], blo[nt][1]);
                }
        }
        __syncthreads();
    }

    #pragma unroll
    for (int mt = 0; mt < 2; ++mt) {
        const int r0 = m0 + wm * 32 + mt * 16 + g;
        #pragma unroll
        for (int nt = 0; nt < 4; ++nt) {
            const int cc = n0 + wn * 32 + nt * 8 + 2 * tig;
            float2 b2 = *(const float2*)&br_p[cc];
            float* c = acc[mt][nt];
            *(float2*)&out[abase + (size_t)r0 * NE + cc] =
                make_float2(c[0] + b2.x, c[1] + b2.y);
            *(float2*)&out[abase + (size_t)(r0 + 8) * NE + cc] =
                make_float2(c[2] + b2.x, c[3] + b2.y);
        }
    }
}

// ---------------------------------------------------------------------------
extern "C" void kernel_launch(void* const* d_in, const int* in_sizes, int n_in,
                              void* d_out, int out_size)
{
    const float* query   = (const float*)d_in[0];
    const float* context = (const float*)d_in[1];
    const float* memory  = (const float*)d_in[2];
    const float* w_logit = (const float*)d_in[3];
    const float* b_logit = (const float*)d_in[4];
    const float* temp    = (const float*)d_in[5];
    const float* w_red   = (const float*)d_in[6];
    const float* b_red   = (const float*)d_in[7];
    float* out = (float*)d_out;

    dim3 g1(NQ / 8, NV / 64, NN);        // 32 x 8 x 4 = 1024 blocks
    k_logits<<<g1, 256>>>(query, context, w_logit, b_logit, temp);

    dim3 g2(4, 4, NN * 2);               // 128 blocks
    k_pv<<<g2, 128>>>(memory);

    dim3 g3(4, 4, NN);                   // 64 blocks
    k_out<<<g3, 128>>>(w_red, b_red, out);
}

// round 12
// speedup vs baseline: 1.5108x; 1.5108x over previous
#include <cuda_runtime.h>
#include <cuda_fp16.h>
#include <cuda_bf16.h>

#define NN 4
#define NQ 256
#define NV 512
#define NE 256

// Scratch (allocation-free requirement)
__device__ float g_expl[NN * NQ * NV];       // exp(logit/t)  (2 MB)
__device__ float g_denp[NN * NQ * 8];        // per-64v denominator partials
__device__ float g_pvp[4][NN * NQ * NE];     // split-4 partials of exp@memory (4 MB)
__device__ float g_heads[NN * NQ * NE];      // normalized, leaky heads (1 MB)
__device__ float g_rdp[4][NN * NQ * NE];     // split-4 partials of heads@Wr^T (4 MB)

// ---------------------------------------------------------------------------
// helpers
// ---------------------------------------------------------------------------
__device__ __forceinline__ uint4 pack8(const float4 a, const float4 b) {
    __half2 h0 = __floats2half2_rn(a.x, a.y);
    __half2 h1 = __floats2half2_rn(a.z, a.w);
    __half2 h2 = __floats2half2_rn(b.x, b.y);
    __half2 h3 = __floats2half2_rn(b.z, b.w);
    uint4 r;
    r.x = *reinterpret_cast<unsigned*>(&h0);
    r.y = *reinterpret_cast<unsigned*>(&h1);
    r.z = *reinterpret_cast<unsigned*>(&h2);
    r.w = *reinterpret_cast<unsigned*>(&h3);
    return r;
}

__device__ __forceinline__ __half2 u2h(unsigned u) {
    return *reinterpret_cast<__half2*>(&u);
}

__device__ __forceinline__ __half2 wtanh(unsigned cv, unsigned qv, unsigned wv) {
    __half2 s = __hadd2(u2h(qv), u2h(cv));
    unsigned su = *reinterpret_cast<unsigned*>(&s);
    unsigned tu;
    asm("tanh.approx.f16x2 %0, %1;" : "=r"(tu) : "r"(su));
    return __hmul2(u2h(tu), u2h(wv));
}

// ---------------------------------------------------------------------------
// K1: e[n,q,v] = exp( (sum_e w*tanh(q+c) + b) / t ), plus per-64v denom
// partials. Warp = q-row, lane pair = (v, v+32): two independent chains
// interleaved for ILP. Full 64-v tile staged once (single sync).
// ct stride 65 uint4 == 4 mod 32 words: same conflict class as r7's [32][33].
// ---------------------------------------------------------------------------
__global__ void __launch_bounds__(256) k_logits(
    const float* __restrict__ q, const float* __restrict__ c,
    const float* __restrict__ wl, const float* __restrict__ bl_p,
    const float* __restrict__ temp_p)
{
    __shared__ uint4 ct[32][65];    // 33.3 KB, [e-octet][v 0..63]
    __shared__ uint4 qs[8][32];     // 4 KB
    __shared__ uint4 ws[32];        // 512 B

    const int n = blockIdx.z;
    const int vb = blockIdx.y;
    const int qbase = blockIdx.x * 8;
    const int tid = threadIdx.x;
    const int wq = tid >> 5, lane = tid & 31;

    {   // one q-octet per thread
        int r = tid >> 5, g = tid & 31;
        const float4* src =
            (const float4*)&q[((size_t)n * NQ + qbase + r) * NE + g * 8];
        qs[r][g] = pack8(src[0], src[1]);
    }
    if (tid < 32) {
        const float4* src = (const float4*)&wl[tid * 8];
        ws[tid] = pack8(src[0], src[1]);
    }
    // stage all 64 v rows (2048 octets)
    const int vbase = vb * 64;
    for (int i = tid; i < 2048; i += 256) {
        int v = i >> 5, g = i & 31;
        const float4* src =
            (const float4*)&c[((size_t)n * NV + vbase + v) * NE + g * 8];
        ct[g][v] = pack8(src[0], src[1]);
    }
    const float bl = __ldg(bl_p);
    const float invt = 1.0f / __ldg(temp_p);
    __syncthreads();

    // two independent v-chains: vl0 = lane, vl1 = lane + 32
    float a0 = 0.f, a1 = 0.f, b0 = 0.f, b1 = 0.f;
    #pragma unroll 4
    for (int g = 0; g < 32; ++g) {
        uint4 qb = qs[wq][g];
        uint4 wb = ws[g];
        uint4 c0 = ct[g][lane];
        uint4 c1 = ct[g][lane + 32];

        __half2 p00 = wtanh(c0.x, qb.x, wb.x);
        __half2 p10 = wtanh(c1.x, qb.x, wb.x);
        __half2 p01 = wtanh(c0.y, qb.y, wb.y);
        __half2 p11 = wtanh(c1.y, qb.y, wb.y);
        __half2 p02 = wtanh(c0.z, qb.z, wb.z);
        __half2 p12 = wtanh(c1.z, qb.z, wb.z);
        __half2 p03 = wtanh(c0.w, qb.w, wb.w);
        __half2 p13 = wtanh(c1.w, qb.w, wb.w);

        __half2 ps0 = __hadd2(__hadd2(p00, p01), __hadd2(p02, p03));
        __half2 ps1 = __hadd2(__hadd2(p10, p11), __hadd2(p12, p13));
        float2 f0 = __half22float2(ps0);
        float2 f1 = __half22float2(ps1);
        a0 += f0.x; a1 += f0.y;
        b0 += f1.x; b1 += f1.y;
    }
    float e0 = __expf((a0 + a1 + bl) * invt);
    float e1 = __expf((b0 + b1 + bl) * invt);
    const size_t rowb = ((size_t)n * NQ + qbase + wq) * NV + vbase;
    g_expl[rowb + lane]      = e0;
    g_expl[rowb + 32 + lane] = e1;

    float dsum = e0 + e1;
    #pragma unroll
    for (int o = 16; o; o >>= 1) dsum += __shfl_xor_sync(0xffffffffu, dsum, o);
    if (lane == 0)
        g_denp[((size_t)n * NQ + qbase + wq) * 8 + vb] = dsum;
}

// ---------------------------------------------------------------------------
// K2: split-4(K-slice 128) of e @ memory. BK=16, 4x4 micro, plain fmaf
// (r2/r7-proven loop shape).
// ---------------------------------------------------------------------------
__global__ void __launch_bounds__(256) k_pv(const float* __restrict__ Mm)
{
    const int n = blockIdx.z >> 2, s = blockIdx.z & 3;
    const int m0 = blockIdx.y * 64, n0 = blockIdx.x * 64;
    const float* A = g_expl + (size_t)n * NQ * NV;
    const float* B = Mm + (size_t)n * NV * NE;

    __shared__ float As[16][68];
    __shared__ float Bs[16][68];

    const int tid = threadIdx.x;
    const int tx = tid & 15, ty = tid >> 4;
    const int ar = tid >> 2, ac = (tid & 3) * 4;
    const int br = tid >> 4, bc = (tid & 15) * 4;

    float acc[4][4] = {};

    for (int k0 = s * 128; k0 < s * 128 + 128; k0 += 16) {
        float4 av = *(const float4*)&A[(size_t)(m0 + ar) * NV + k0 + ac];
        As[ac][ar]     = av.x; As[ac + 1][ar] = av.y;
        As[ac + 2][ar] = av.z; As[ac + 3][ar] = av.w;
        *(float4*)&Bs[br][bc] =
            *(const float4*)&B[(size_t)(k0 + br) * NE + n0 + bc];
        __syncthreads();
        #pragma unroll
        for (int k = 0; k < 16; ++k) {
            float a[4], b[4];
            *(float4*)a = *(const float4*)&As[k][ty * 4];
            *(float4*)b = *(const float4*)&Bs[k][tx * 4];
            #pragma unroll
            for (int i = 0; i < 4; ++i)
                #pragma unroll
                for (int j = 0; j < 4; ++j)
                    acc[i][j] += a[i] * b[j];
        }
        __syncthreads();
    }

    float* P = g_pvp[s] + (size_t)n * NQ * NE;
    #pragma unroll
    for (int i = 0; i < 4; ++i)
        *(float4*)&P[(size_t)(m0 + ty * 4 + i) * NE + n0 + tx * 4] =
            make_float4(acc[i][0], acc[i][1], acc[i][2], acc[i][3]);
}

// ---------------------------------------------------------------------------
// K3: heads = leaky( (sum_s pvp) / (sum_vb denp) )
// ---------------------------------------------------------------------------
__global__ void __launch_bounds__(256) k_merge()
{
    const int i = blockIdx.x * 256 + threadIdx.x;   // float4 idx, 65536 total
    const int row = i >> 6;

    float dt = 0.f;
    #pragma unroll
    for (int vb = 0; vb < 8; ++vb) dt += g_denp[(size_t)row * 8 + vb];
    const float inv = 1.0f / dt;

    float4 sv = make_float4(0.f, 0.f, 0.f, 0.f);
    #pragma unroll
    for (int sp = 0; sp < 4; ++sp) {
        float4 p = *(const float4*)&g_pvp[sp][(size_t)i * 4];
        sv.x += p.x; sv.y += p.y; sv.z += p.z; sv.w += p.w;
    }
    float h0 = sv.x * inv, h1 = sv.y * inv, h2 = sv.z * inv, h3 = sv.w * inv;
    float4 r;
    r.x = (h0 > 0.f) ? h0 : 0.01f * h0;
    r.y = (h1 > 0.f) ? h1 : 0.01f * h1;
    r.z = (h2 > 0.f) ? h2 : 0.01f * h2;
    r.w = (h3 > 0.f) ? h3 : 0.01f * h3;
    *(float4*)&g_heads[(size_t)i * 4] = r;
}

// ---------------------------------------------------------------------------
// K4: split-4(K-slice 64) of heads @ Wr^T. 64x64 tiles, BK=16, 4x4 micro.
// ---------------------------------------------------------------------------
__global__ void __launch_bounds__(256) k_out(const float* __restrict__ Wr)
{
    const int n = blockIdx.z >> 2, s = blockIdx.z & 3;
    const int m0 = blockIdx.y * 64, n0 = blockIdx.x * 64;
    const float* A = g_heads + (size_t)n * NQ * NE;

    __shared__ float As[16][68];
    __shared__ float Bs[16][68];

    const int tid = threadIdx.x;
    const int tx = tid & 15, ty = tid >> 4;
    const int ar = tid >> 2, ac = (tid & 3) * 4;

    float acc[4][4] = {};

    for (int k0 = s * 64; k0 < s * 64 + 64; k0 += 16) {
        float4 av = *(const float4*)&A[(size_t)(m0 + ar) * NE + k0 + ac];
        As[ac][ar]     = av.x; As[ac + 1][ar] = av.y;
        As[ac + 2][ar] = av.z; As[ac + 3][ar] = av.w;
        float4 bv = *(const float4*)&Wr[(size_t)(n0 + ar) * NE + k0 + ac];
        Bs[ac][ar]     = bv.x; Bs[ac + 1][ar] = bv.y;
        Bs[ac + 2][ar] = bv.z; Bs[ac + 3][ar] = bv.w;
        __syncthreads();
        #pragma unroll
        for (int k = 0; k < 16; ++k) {
            float a[4], b[4];
            *(float4*)a = *(const float4*)&As[k][ty * 4];
            *(float4*)b = *(const float4*)&Bs[k][tx * 4];
            #pragma unroll
            for (int i = 0; i < 4; ++i)
                #pragma unroll
                for (int j = 0; j < 4; ++j)
                    acc[i][j] += a[i] * b[j];
        }
        __syncthreads();
    }

    float* R = g_rdp[s] + (size_t)n * NQ * NE;
    #pragma unroll
    for (int i = 0; i < 4; ++i)
        *(float4*)&R[(size_t)(m0 + ty * 4 + i) * NE + n0 + tx * 4] =
            make_float4(acc[i][0], acc[i][1], acc[i][2], acc[i][3]);
}

// ---------------------------------------------------------------------------
// K5: out = sum of 4 reduce-partials + bias
// ---------------------------------------------------------------------------
__global__ void __launch_bounds__(256) k_final(
    const float* __restrict__ br_p, float* __restrict__ out)
{
    const int i = blockIdx.x * 256 + threadIdx.x;   // float4 idx, 65536 total
    const int col4 = i & 63;
    float4 r = *(const float4*)&br_p[col4 * 4];
    #pragma unroll
    for (int sp = 0; sp < 4; ++sp) {
        float4 p = *(const float4*)&g_rdp[sp][(size_t)i * 4];
        r.x += p.x; r.y += p.y; r.z += p.z; r.w += p.w;
    }
    *(float4*)&out[(size_t)i * 4] = r;
}

// ---------------------------------------------------------------------------
extern "C" void kernel_launch(void* const* d_in, const int* in_sizes, int n_in,
                              void* d_out, int out_size)
{
    const float* query   = (const float*)d_in[0];
    const float* context = (const float*)d_in[1];
    const float* memory  = (const float*)d_in[2];
    const float* w_logit = (const float*)d_in[3];
    const float* b_logit = (const float*)d_in[4];
    const float* temp    = (const float*)d_in[5];
    const float* w_red   = (const float*)d_in[6];
    const float* b_red   = (const float*)d_in[7];
    float* out = (float*)d_out;

    dim3 g1(NQ / 8, NV / 64, NN);        // 32 x 8 x 4 = 1024 blocks
    k_logits<<<g1, 256>>>(query, context, w_logit, b_logit, temp);

    dim3 g2(NE / 64, NQ / 64, NN * 4);   // 4 x 4 x 16 = 256 blocks
    k_pv<<<g2, 256>>>(memory);

    k_merge<<<256, 256>>>();             // 65536 float4

    dim3 g4(NE / 64, NQ / 64, NN * 4);   // 256 blocks
    k_out<<<g4, 256>>>(w_red);

    k_final<<<256, 256>>>(b_red, out);
}